// round 5
// baseline (speedup 1.0000x reference)
#include <cuda_runtime.h>
#include <cuda_bf16.h>
#include <math.h>

// Problem constants
// B=64, L=500, F=256, H=4, dk=64
// rows (B*L) = 32000 ; bh-rows (B*H*L) = 128000

// -------------------- device scratch (no allocations allowed) --------------------
__device__ float g_wcomb[256 * 256];                    // folded W_qs @ (blockdiag W1)
__device__ float g_weight[64 * 4 * 500 * 64];           // relu(q@Wcomb+b1), layout [(b*4+h)*500+l][64]
__device__ float g_vh[64 * 4 * 500 * 64];               // v@W_vs,            layout [(b*4+h)*500+l][64]
__device__ float g_S[128000ull * 500];                  // logits -> softmax probs (in place)
__device__ float g_attn[32000ull * 256];                // attn@vh, heads concatenated [b*500+l][h*64+d]
__device__ float g_tmp[32000ull * 256];                 // pre-LayerNorm

// -------------------- kernel 0: W_comb[kin][h*64+d] = sum_e W_qs[kin][h*64+e] * W1[e][d] ----------
__global__ void wcomb_kernel(const float* __restrict__ w_qs,
                             const float* __restrict__ w1,
                             float* __restrict__ out) {
    int kin = blockIdx.x;        // 0..255
    int c   = threadIdx.x;       // 0..255
    int h = c >> 6, d = c & 63;
    const float* wq = w_qs + kin * 256 + (h << 6);
    float acc = 0.f;
#pragma unroll 8
    for (int e = 0; e < 64; e++)
        acc = fmaf(wq[e], w1[(e << 6) + d], acc);
    out[kin * 256 + c] = acc;
}

// -------------------- generic tiled SGEMM: 64x64 block, 4x4 per thread, BK=16 --------------------
// MODE 0: weight = relu(acc + b1[d]); store [(b*4+h)*500+l][d]
// MODE 1: vh     = acc;               store [(b*4+h)*500+l][d]
// MODE 2: S      = acc + b2[c];       store row*500 + c    (c < 500 guard)
// MODE 3: batched (z = b*4+h): attn_out = acc; store [(b*500+l)*256 + h*64 + d]
// MODE 4: tmp    = acc + resid[row*256+c]
template <int MODE>
__global__ __launch_bounds__(256) void sgemm_k(
    const float* __restrict__ A, const float* __restrict__ B,
    float* __restrict__ C, int M, int N, int K, int lda, int ldb,
    const float* __restrict__ bias, const float* __restrict__ resid)
{
    if (MODE == 3) {
        int batch = blockIdx.z;
        A += (size_t)batch * 500 * 500;
        B += (size_t)batch * 500 * 64;
    }
    __shared__ float As[16][68];   // stored transposed: As[k][row]
    __shared__ float Bs[16][68];   // Bs[k][col]

    const int tid = threadIdx.x;
    const int tx = tid & 15, ty = tid >> 4;
    const int r0 = blockIdx.x * 64, c0 = blockIdx.y * 64;

    const int aRow = tid >> 2, aK = (tid & 3) << 2;
    const int bRow = tid >> 4, bCol = (tid & 15) << 2;

    float acc[4][4] = {};

    for (int kt = 0; kt < K; kt += 16) {
        // ---- load A tile (row-major) -> transposed smem ----
        float4 av = make_float4(0.f, 0.f, 0.f, 0.f);
        {
            int ar = r0 + aRow, ak = kt + aK;
            if (ar < M) {
                const float* ap = A + (size_t)ar * lda;
                if (ak + 3 < K) {
                    av = *(const float4*)(ap + ak);
                } else {
                    if (ak     < K) av.x = ap[ak];
                    if (ak + 1 < K) av.y = ap[ak + 1];
                    if (ak + 2 < K) av.z = ap[ak + 2];
                    if (ak + 3 < K) av.w = ap[ak + 3];
                }
            }
        }
        As[aK + 0][aRow] = av.x;
        As[aK + 1][aRow] = av.y;
        As[aK + 2][aRow] = av.z;
        As[aK + 3][aRow] = av.w;

        // ---- load B tile (row-major KxN) ----
        float4 bv = make_float4(0.f, 0.f, 0.f, 0.f);
        {
            int bk = kt + bRow, bc = c0 + bCol;
            if (bk < K && bc < N) {
                const float* bp = B + (size_t)bk * ldb;
                if (bc + 3 < N) {
                    bv = *(const float4*)(bp + bc);
                } else {
                    bv.x = bp[bc];
                    if (bc + 1 < N) bv.y = bp[bc + 1];
                    if (bc + 2 < N) bv.z = bp[bc + 2];
                }
            }
        }
        *(float4*)&Bs[bRow][bCol] = bv;

        __syncthreads();

#pragma unroll
        for (int k = 0; k < 16; k++) {
            float4 a4 = *(const float4*)&As[k][ty << 2];
            float4 b4 = *(const float4*)&Bs[k][tx << 2];
            float a[4] = {a4.x, a4.y, a4.z, a4.w};
            float b[4] = {b4.x, b4.y, b4.z, b4.w};
#pragma unroll
            for (int i = 0; i < 4; i++)
#pragma unroll
                for (int j = 0; j < 4; j++)
                    acc[i][j] = fmaf(a[i], b[j], acc[i][j]);
        }
        __syncthreads();
    }

    // ---- epilogue ----
#pragma unroll
    for (int i = 0; i < 4; i++) {
        int r = r0 + (ty << 2) + i;
        if (r >= M) continue;
#pragma unroll
        for (int j = 0; j < 4; j++) {
            int c = c0 + (tx << 2) + j;
            if (c >= N) continue;
            float v = acc[i][j];
            if (MODE == 0) {
                int bi = r / 500, l = r % 500;
                int h = c >> 6, d = c & 63;
                v = fmaxf(v + bias[d], 0.f);
                C[(((size_t)(bi * 4 + h) * 500 + l) << 6) + d] = v;
            } else if (MODE == 1) {
                int bi = r / 500, l = r % 500;
                int h = c >> 6, d = c & 63;
                C[(((size_t)(bi * 4 + h) * 500 + l) << 6) + d] = v;
            } else if (MODE == 2) {
                C[(size_t)r * 500 + c] = v + bias[c];
            } else if (MODE == 3) {
                int batch = blockIdx.z;
                int bi = batch >> 2, h = batch & 3;
                C[((size_t)(bi * 500 + r) << 8) + (h << 6) + c] = v;
            } else { // MODE 4
                C[(size_t)r * 256 + c] = v + resid[(size_t)r * 256 + c];
            }
        }
    }
}

// -------------------- softmax over rows of length 500, in place --------------------
__global__ __launch_bounds__(128) void softmax_kernel(float* __restrict__ S) {
    float* p = S + (size_t)blockIdx.x * 500;
    const int t = threadIdx.x;
    float v[4];
    float mx = -3.4e38f;
#pragma unroll
    for (int i = 0; i < 4; i++) {
        int j = t + (i << 7);
        v[i] = (j < 500) ? p[j] : -3.4e38f;
        mx = fmaxf(mx, v[i]);
    }
#pragma unroll
    for (int o = 16; o > 0; o >>= 1)
        mx = fmaxf(mx, __shfl_xor_sync(0xffffffffu, mx, o));
    __shared__ float red[4];
    if ((t & 31) == 0) red[t >> 5] = mx;
    __syncthreads();
    mx = fmaxf(fmaxf(red[0], red[1]), fmaxf(red[2], red[3]));

    float s = 0.f;
#pragma unroll
    for (int i = 0; i < 4; i++) {
        v[i] = __expf(v[i] - mx);   // padded lanes: exp(-huge) -> 0
        s += v[i];
    }
#pragma unroll
    for (int o = 16; o > 0; o >>= 1)
        s += __shfl_xor_sync(0xffffffffu, s, o);
    __syncthreads();
    if ((t & 31) == 0) red[t >> 5] = s;
    __syncthreads();
    float tot = red[0] + red[1] + red[2] + red[3];
    float inv = 1.0f / tot;
#pragma unroll
    for (int i = 0; i < 4; i++) {
        int j = t + (i << 7);
        if (j < 500) p[j] = v[i] * inv;
    }
}

// -------------------- LayerNorm over F=256, one block per row --------------------
__global__ __launch_bounds__(256) void ln_kernel(const float* __restrict__ X,
                                                 const float* __restrict__ gw,
                                                 const float* __restrict__ bw,
                                                 float* __restrict__ out) {
    size_t base = (size_t)blockIdx.x << 8;
    const int t = threadIdx.x;
    float x = X[base + t];
    float s = x, s2 = x * x;
#pragma unroll
    for (int o = 16; o > 0; o >>= 1) {
        s  += __shfl_xor_sync(0xffffffffu, s,  o);
        s2 += __shfl_xor_sync(0xffffffffu, s2, o);
    }
    __shared__ float rs[8], rs2[8];
    if ((t & 31) == 0) { rs[t >> 5] = s; rs2[t >> 5] = s2; }
    __syncthreads();
    s = 0.f; s2 = 0.f;
#pragma unroll
    for (int w = 0; w < 8; w++) { s += rs[w]; s2 += rs2[w]; }
    float mean = s * (1.f / 256.f);
    float var  = s2 * (1.f / 256.f) - mean * mean;
    float r = rsqrtf(var + 1e-6f);
    out[base + t] = (x - mean) * r * gw[t] + bw[t];
}

// -------------------- launch --------------------
extern "C" void kernel_launch(void* const* d_in, const int* in_sizes, int n_in,
                              void* d_out, int out_size) {
    const float* q    = (const float*)d_in[0];
    // d_in[1] = k : unused by the reference computation
    const float* v    = (const float*)d_in[2];
    const float* w_qs = (const float*)d_in[3];
    const float* w_vs = (const float*)d_in[4];
    const float* w1   = (const float*)d_in[5];
    const float* b1   = (const float*)d_in[6];
    const float* w2   = (const float*)d_in[7];
    const float* b2   = (const float*)d_in[8];
    const float* fc_w = (const float*)d_in[9];
    const float* ln_g = (const float*)d_in[10];
    const float* ln_b = (const float*)d_in[11];
    float* out = (float*)d_out;

    float *wcomb, *weight, *vh, *S, *attn, *tmp;
    cudaGetSymbolAddress((void**)&wcomb,  g_wcomb);
    cudaGetSymbolAddress((void**)&weight, g_weight);
    cudaGetSymbolAddress((void**)&vh,     g_vh);
    cudaGetSymbolAddress((void**)&S,      g_S);
    cudaGetSymbolAddress((void**)&attn,   g_attn);
    cudaGetSymbolAddress((void**)&tmp,    g_tmp);

    // 0) fold W_qs @ blockdiag(W1) -> Wcomb  (relu applied after, so exact)
    wcomb_kernel<<<256, 256>>>(w_qs, w1, wcomb);

    // 1) weight = relu(q @ Wcomb + b1), stored per (b,h) contiguous
    sgemm_k<0><<<dim3(500, 4, 1), 256>>>(q, wcomb, weight,
                                         32000, 256, 256, 256, 256, b1, nullptr);

    // 2) vh = v @ W_vs, stored per (b,h) contiguous
    sgemm_k<1><<<dim3(500, 4, 1), 256>>>(v, w_vs, vh,
                                         32000, 256, 256, 256, 256, nullptr, nullptr);

    // 3) S = weight @ W2 + b2   (M=128000, N=500, K=64)
    sgemm_k<2><<<dim3(2000, 8, 1), 256>>>(weight, w2, S,
                                          128000, 500, 64, 64, 500, b2, nullptr);

    // 4) softmax rows of S in place
    softmax_kernel<<<128000, 128>>>(S);

    // 5) attn_out = P @ vh, batched over 256 (b,h) pairs
    sgemm_k<3><<<dim3(8, 1, 256), 256>>>(S, vh, attn,
                                         500, 64, 500, 500, 64, nullptr, nullptr);

    // 6) tmp = attn_out @ fc_w + q (residual)
    sgemm_k<4><<<dim3(500, 4, 1), 256>>>(attn, fc_w, tmp,
                                         32000, 256, 256, 256, 256, nullptr, q);

    // 7) LayerNorm -> output
    ln_kernel<<<32000, 256>>>(tmp, ln_g, ln_b, out);
}